// round 3
// baseline (speedup 1.0000x reference)
#include <cuda_runtime.h>

// Problem constants (static in the reference: SIZES[g] = 256 + 16*g, B=16)
#define NB 16
#define IN_DIM 16
#define HID 64
#define OUTD 32
#define N_TOT 6016
#define N_PAIRS 2349056

// t scratch: per-node MLP output [N_TOT, 32] = 770 KB
__device__ float g_t[N_TOT * OUTD];

// starts[g] = sum_{h<g} sizes[h]; starts[16] = 6016 (sentinel)
__constant__ int c_starts[NB + 1] = {
    0, 256, 528, 816, 1120, 1440, 1776, 2128,
    2496, 2880, 3280, 3696, 4128, 4576, 5040, 5520, 6016};
__constant__ int c_sizes[NB] = {
    256, 272, 288, 304, 320, 336, 352, 368,
    384, 400, 416, 432, 448, 464, 480, 496};
// pair_cum[g] = sum_{h<g} sizes[h]^2
__constant__ int c_paircum[NB] = {
    0, 65536, 139520, 222464, 314880, 417280, 530176, 654080,
    789504, 936960, 1096960, 1270016, 1456640, 1657344, 1872640, 2103040};

// ---------------------------------------------------------------------------
// Kernel 1: per-node MLP  t[n] = relu(ape[n] @ W1 + b1) @ W2 + b2
// One thread per node; weights staged in shared; hidden values streamed so the
// live register set stays at ~ (16 input + 32 accum + temps).
// ---------------------------------------------------------------------------
__global__ __launch_bounds__(128) void mlp_kernel(
    const float* __restrict__ ape, const float* __restrict__ W1,
    const float* __restrict__ b1, const float* __restrict__ W2,
    const float* __restrict__ b2)
{
    __shared__ float sW1[IN_DIM * HID];   // [k][h] row-major, 4 KB
    __shared__ float sW2[HID * OUTD];     // [h][o] row-major, 8 KB
    __shared__ float sb1[HID];
    __shared__ float sb2[OUTD];

    const int tid = threadIdx.x;
    for (int i = tid; i < IN_DIM * HID; i += blockDim.x) sW1[i] = W1[i];
    for (int i = tid; i < HID * OUTD; i += blockDim.x) sW2[i] = W2[i];
    if (tid < HID)  sb1[tid] = b1[tid];
    if (tid < OUTD) sb2[tid] = b2[tid];
    __syncthreads();

    const int n = blockIdx.x * blockDim.x + tid;
    if (n >= N_TOT) return;

    float a[IN_DIM];
    const float4* ap = reinterpret_cast<const float4*>(ape + (size_t)n * IN_DIM);
#pragma unroll
    for (int k4 = 0; k4 < IN_DIM / 4; k4++) {
        float4 v = __ldg(ap + k4);
        a[k4 * 4 + 0] = v.x; a[k4 * 4 + 1] = v.y;
        a[k4 * 4 + 2] = v.z; a[k4 * 4 + 3] = v.w;
    }

    float acc[OUTD];
#pragma unroll
    for (int o = 0; o < OUTD; o++) acc[o] = sb2[o];

#pragma unroll 4
    for (int h = 0; h < HID; h++) {
        float hh = sb1[h];
#pragma unroll
        for (int k = 0; k < IN_DIM; k++) hh = fmaf(a[k], sW1[k * HID + h], hh);
        hh = fmaxf(hh, 0.0f);
#pragma unroll
        for (int o = 0; o < OUTD; o++) acc[o] = fmaf(hh, sW2[h * OUTD + o], acc[o]);
    }

    float4* tp = reinterpret_cast<float4*>(g_t + (size_t)n * OUTD);
#pragma unroll
    for (int o4 = 0; o4 < OUTD / 4; o4++)
        tp[o4] = make_float4(acc[o4 * 4 + 0], acc[o4 * 4 + 1],
                             acc[o4 * 4 + 2], acc[o4 * 4 + 3]);
}

// ---------------------------------------------------------------------------
// Kernel 2: pairwise outer-sum, ragged gather order.
// Grid: one block per global node row (b, i). 256 threads = 32 j-lanes x 8 quads.
// out[(pair_cum[b] + i*n_b + j)*32 + q*4 .. +3] = t[row][q*4..] + t[start_b+j][q*4..]
// Warp stores 512 B contiguous -> fully coalesced STG.128.
// ---------------------------------------------------------------------------
__global__ __launch_bounds__(256) void pair_kernel(float* __restrict__ out)
{
    const int row = blockIdx.x;

    // which graph does this row belong to (16-entry unrolled scan, constant mem)
    int b = 0;
#pragma unroll
    for (int g = 1; g < NB; g++) b += (row >= c_starts[g]) ? 1 : 0;

    const int gbase = c_starts[b];
    const int nb    = c_sizes[b];
    const int i     = row - gbase;
    const int orow0 = c_paircum[b] + i * nb;   // first output row for this (b,i)

    const int q  = threadIdx.x & 7;    // quad index (q*4 .. q*4+3 of the 32 outs)
    const int jl = threadIdx.x >> 3;   // j lane (0..31)

    const float4 ti = *reinterpret_cast<const float4*>(g_t + (size_t)row * OUTD + q * 4);

    for (int j = jl; j < nb; j += 32) {
        const float4 tj = __ldg(reinterpret_cast<const float4*>(
            g_t + (size_t)(gbase + j) * OUTD + q * 4));
        float4 r;
        r.x = ti.x + tj.x; r.y = ti.y + tj.y;
        r.z = ti.z + tj.z; r.w = ti.w + tj.w;
        __stcs(reinterpret_cast<float4*>(
                   out + (size_t)(orow0 + j) * OUTD + q * 4), r);
    }
}

extern "C" void kernel_launch(void* const* d_in, const int* in_sizes, int n_in,
                              void* d_out, int out_size)
{
    const float* ape = (const float*)d_in[0];
    const float* W1  = (const float*)d_in[1];
    const float* b1  = (const float*)d_in[2];
    const float* W2  = (const float*)d_in[3];
    const float* b2  = (const float*)d_in[4];
    float* out = (float*)d_out;

    mlp_kernel<<<(N_TOT + 127) / 128, 128>>>(ape, W1, b1, W2, b2);
    pair_kernel<<<N_TOT, 256>>>(out);
}